// round 15
// baseline (speedup 1.0000x reference)
#include <cuda_runtime.h>
#include <cuda_fp16.h>
#include <math.h>
#include <stdint.h>

#define BATCH 8
#define NPTS  4096
#define DIM   64
#define NT    32                       // 4096 / 128 row-strips
#define NTRI  (NT * (NT + 1) / 2)      // 528 super-tiles (128x128) per batch
#define NJOBS (2 * NTRI)               // 1056 half-jobs (128x64) per batch
#define SLOTS 55                       // CTAs per batch
#define GRID  (BATCH * SLOTS)          // 440 (3 CTAs/SM x 148 = 444 >= 440, 1 wave)
#define TPB   256

// smem rows: 144 B stride (72 fp16) -> conflict-free ldmatrix/STS
#define SROWB   144
#define A_BYTES (128 * SROWB)          // 18432 (A strip: 128 rows)
#define B_BYTES (64 * SROWB)           //  9216 (B half-strip: 64 rows)
#define BUFSZ   (A_BYTES + B_BYTES)    // 27648
#define NBUF    2
#define SMEM_BYTES (NBUF * BUFSZ)      // 55296 -> 3 CTAs/SM

// Single array scaled by sqrt(0.5*log2(e)): (s*a)·(s*b) = 0.5*log2(e)*a·b
__device__ __align__(16) __half g_s[BATCH * NPTS * DIM];
__device__ double g_partials[GRID];
__device__ unsigned g_cnt = 0;

__device__ __forceinline__ uint32_t smem_u32(const void* p) {
    uint32_t a;
    asm("{ .reg .u64 t; cvta.to.shared.u64 t, %1; cvt.u32.u64 %0, t; }" : "=r"(a) : "l"(p));
    return a;
}
template <int IMM>
__device__ __forceinline__ void ldsm4i(uint32_t* r, uint32_t addr) {
    asm volatile("ldmatrix.sync.aligned.m8n8.x4.shared.b16 {%0,%1,%2,%3}, [%4+%5];"
                 : "=r"(r[0]), "=r"(r[1]), "=r"(r[2]), "=r"(r[3])
                 : "r"(addr), "n"(IMM));
}
__device__ __forceinline__ void mma_acc(float* d, const uint32_t* a, const uint32_t* b) {
    asm("mma.sync.aligned.m16n8k16.row.col.f32.f16.f16.f32 "
        "{%0,%1,%2,%3}, {%4,%5,%6,%7}, {%8,%9}, {%0,%1,%2,%3};"
        : "+f"(d[0]), "+f"(d[1]), "+f"(d[2]), "+f"(d[3])
        : "r"(a[0]), "r"(a[1]), "r"(a[2]), "r"(a[3]), "r"(b[0]), "r"(b[1]));
}
__device__ __forceinline__ void mma_zro(float* d, const uint32_t* a, const uint32_t* b) {
    asm("mma.sync.aligned.m16n8k16.row.col.f32.f16.f16.f32 "
        "{%0,%1,%2,%3}, {%4,%5,%6,%7}, {%8,%9}, {%10,%10,%10,%10};"
        : "=f"(d[0]), "=f"(d[1]), "=f"(d[2]), "=f"(d[3])
        : "r"(a[0]), "r"(a[1]), "r"(a[2]), "r"(a[3]), "r"(b[0]), "r"(b[1]), "f"(0.0f));
}
template <int DI, int SI>
__device__ __forceinline__ void cp16i(uint32_t dst, const __half* src) {
    asm volatile("cp.async.ca.shared.global [%0+%2], [%1+%3], 16;"
                 :: "r"(dst), "l"(src), "n"(DI), "n"(SI));
}
__device__ __forceinline__ float ex2f(float x) {
    float e;
    asm("ex2.approx.f32 %0, %1;" : "=f"(e) : "f"(x));
    return e;
}

// ---------------- 1) convert f32 -> fp16 scaled by sqrt(0.5*log2e) ----------------
__global__ __launch_bounds__(256) void split_kernel(const float* __restrict__ emb) {
    const float SQC = 0.84932180612318867f;  // sqrt(0.5*log2(e))
    int i = (blockIdx.x * 256 + threadIdx.x) * 4;
    float4 v = *(const float4*)(emb + i);
    float x[4] = {v.x, v.y, v.z, v.w};
    __half s[4];
    #pragma unroll
    for (int j = 0; j < 4; ++j) s[j] = __float2half(x[j] * SQC);
    *(uint2*)&g_s[i] = *(uint2*)s;
}

// ---------------- 2) persistent HMMA half-tile kernel (fused finalize) ----------------
// A strip: 128 rows (4 cp16/thread); B half-strip: 64 rows (2 cp16/thread).
// Diagonal super: B rows are a subset of A rows -> skip B load, alias into A region.
__device__ __forceinline__ void load_job(uint32_t dst, const __half* sA, const __half* sB,
                                         bool dg) {
    cp16i<0 * SROWB, 0 * DIM * 2>(dst, sA);
    cp16i<32 * SROWB, 32 * DIM * 2>(dst, sA);
    cp16i<64 * SROWB, 64 * DIM * 2>(dst, sA);
    cp16i<96 * SROWB, 96 * DIM * 2>(dst, sA);
    if (!dg) {
        cp16i<A_BYTES + 0 * SROWB, 0 * DIM * 2>(dst, sB);
        cp16i<A_BYTES + 32 * SROWB, 32 * DIM * 2>(dst, sB);
    }
    asm volatile("cp.async.commit_group;" ::: "memory");
}

// k-steps 1..3 for the 128x64 job: 4 A-frags x 2 nb, 5 ldsm + 8 mma per step.
#define KSTEP_H(KO)                                                              \
    {                                                                            \
        uint32_t A[4][4], B[4];                                                  \
        ldsm4i<KO>(A[0], aA0); ldsm4i<KO>(A[1], aA1);                            \
        ldsm4i<KO>(A[2], aA2); ldsm4i<KO>(A[3], aA3);                            \
        ldsm4i<KO>(B, aB0);                                                      \
        _Pragma("unroll")                                                        \
        for (int f = 0; f < 4; ++f) {                                            \
            mma_acc(acc[f][0], A[f], &B[0]);                                     \
            mma_acc(acc[f][1], A[f], &B[2]);                                     \
        }                                                                        \
    }

__global__ __launch_bounds__(TPB, 3) void tile_kernel(float* __restrict__ out) {
    extern __shared__ __align__(128) char smem[];
    __shared__ double redbuf[8];
    __shared__ int is_last_s;
    const uint32_t sbase = smem_u32(smem);
    const int tid = threadIdx.x;
    const int wid = tid >> 5;
    const int lid = tid & 31;
    const int wa = wid & 1;            // A-row half: 0-63 / 64-127
    const int wb = wid >> 1;           // B-row group of 16 within 64

    const int bb   = blockIdx.x & 7;   // fixed batch per CTA
    const int slot = blockIdx.x >> 3;  // 0..54
    const __half* gS = g_s + (size_t)bb * NPTS * DIM;

    const int srcoff = (tid >> 3) * DIM + (tid & 7) * 8;                 // elements
    const uint32_t dsto = (uint32_t)((tid >> 3) * SROWB + (tid & 7) * 16);

    uint32_t offA[4];
    {
        int row = ((lid >> 3) & 1) * 8 + (lid & 7);
        int kc  = (lid >> 4) * 16;     // bytes
        #pragma unroll
        for (int f = 0; f < 4; ++f)
            offA[f] = (uint32_t)((wa * 64 + f * 16 + row) * SROWB + kc);
    }
    uint32_t offB;                     // relative to B region base
    {
        int row = (lid >> 4) * 8 + (lid & 7);
        int kc  = ((lid >> 3) & 1) * 16;
        offB = (uint32_t)((wb * 16 + row) * SROWB + kc);
    }

    float facc = 0.0f;                 // running per-thread sum (all positive)
    float pw   = 0.0f;                 // weight of pending (previous) job; 0 = none
    float acc[4][2][4];
    #pragma unroll
    for (int f = 0; f < 4; ++f)
        #pragma unroll
        for (int nb = 0; nb < 2; ++nb)
            #pragma unroll
            for (int e = 0; e < 4; ++e) acc[f][nb][e] = 0.0f;

    // job = 2*t + h; t = super-tile tri index (tn <= tm), h = B half.
    int job = slot;
    int t = job >> 1, h = job & 1;
    int tn = t, tm = 0;
    while (tn > tm) { tn -= (tm + 1); ++tm; }

    load_job(sbase + dsto, gS + tn * (128 * DIM) + srcoff,
             gS + (tm * 128 + h * 64) * DIM + srcoff, tn == tm);

    int buf = 0;
    for (; job < NJOBS; ) {
        const int cdiag = (tn == tm);
        const int ch = h;
        const int jn = job + SLOTS;
        asm volatile("cp.async.wait_group 0;" ::: "memory");  // our copies done
        __syncthreads();               // (1) everyone's copies visible; prev compute done
        if (jn < NJOBS) {
            int dt = (jn >> 1) - (job >> 1);
            tn += dt;
            while (tn > tm) { tn -= (tm + 1); ++tm; }
            h = jn & 1;
            load_job(sbase + (buf ^ 1) * BUFSZ + dsto,
                     gS + tn * (128 * DIM) + srcoff,
                     gS + (tm * 128 + h * 64) * DIM + srcoff, tn == tm);
        }

        const uint32_t bufbase = sbase + buf * BUFSZ;
        const uint32_t aA0 = bufbase + offA[0], aA1 = bufbase + offA[1];
        const uint32_t aA2 = bufbase + offA[2], aA3 = bufbase + offA[3];
        const uint32_t aB0 = bufbase + (cdiag ? (uint32_t)(ch * 64 * SROWB)
                                              : (uint32_t)A_BYTES) + offB;

        float s0 = 0.f, s1 = 0.f, s2 = 0.f, s3 = 0.f;
        // kstep 0 interleaved with the previous job's ex2 epilogue (per-f chunks
        // ahead of each acc[f] overwrite) -> MUFU fills the HMMA/ldsm shadow.
        {
            uint32_t A[4][4], B[4];
            ldsm4i<0>(A[0], aA0); ldsm4i<0>(A[1], aA1);
            ldsm4i<0>(A[2], aA2); ldsm4i<0>(A[3], aA3);
            ldsm4i<0>(B, aB0);
            #pragma unroll
            for (int f = 0; f < 4; ++f) {
                #pragma unroll
                for (int nb = 0; nb < 2; ++nb) {
                    s0 += ex2f(acc[f][nb][0]);
                    s1 += ex2f(acc[f][nb][1]);
                    s2 += ex2f(acc[f][nb][2]);
                    s3 += ex2f(acc[f][nb][3]);
                }
                mma_zro(acc[f][0], A[f], &B[0]);
                mma_zro(acc[f][1], A[f], &B[2]);
            }
        }
        facc += pw * ((s0 + s1) + (s2 + s3));  // pw=0 on first iteration

        KSTEP_H(32)
        KSTEP_H(64)
        KSTEP_H(96)

        __syncthreads();               // (2) all warps done reading buf -> re-writable

        pw = cdiag ? 1.0f : 2.0f;
        buf ^= 1;
        job = jn;
    }

    // Final pending epilogue.
    {
        float s0 = 0.f, s1 = 0.f, s2 = 0.f, s3 = 0.f;
        #pragma unroll
        for (int f = 0; f < 4; ++f)
            #pragma unroll
            for (int nb = 0; nb < 2; ++nb) {
                s0 += ex2f(acc[f][nb][0]);
                s1 += ex2f(acc[f][nb][1]);
                s2 += ex2f(acc[f][nb][2]);
                s3 += ex2f(acc[f][nb][3]);
            }
        facc += pw * ((s0 + s1) + (s2 + s3));
    }

    // One block reduction in double at the very end.
    double acc_d = (double)facc;
    #pragma unroll
    for (int o = 16; o > 0; o >>= 1)
        acc_d += __shfl_down_sync(0xffffffffu, acc_d, o);
    if (lid == 0) redbuf[wid] = acc_d;
    __syncthreads();
    if (tid == 0) {
        double v = ((redbuf[0] + redbuf[1]) + (redbuf[2] + redbuf[3])) +
                   ((redbuf[4] + redbuf[5]) + (redbuf[6] + redbuf[7]));
        g_partials[blockIdx.x] = v;
    }

    // Fused finalize: last CTA reduces per-batch and writes the loss.
    __threadfence();
    if (tid == 0) {
        unsigned o = atomicAdd(&g_cnt, 1u);
        is_last_s = (o == GRID - 1) ? 1 : 0;
    }
    __syncthreads();
    if (is_last_s) {
        __threadfence();
        const int w = wid;             // warp w handles batch w
        double s = 0.0;
        for (int i = lid; i < SLOTS; i += 32)
            s += g_partials[(i << 3) + w];
        #pragma unroll
        for (int o = 16; o > 0; o >>= 1)
            s += __shfl_down_sync(0xffffffffu, s, o);
        if (lid == 0) redbuf[w] = log(s);
        __syncthreads();
        if (tid == 0) {
            double L = ((redbuf[0] + redbuf[1]) + (redbuf[2] + redbuf[3])) +
                       ((redbuf[4] + redbuf[5]) + (redbuf[6] + redbuf[7]));
            *out = (float)(L / 8.0);
            g_cnt = 0;                 // reset for next graph replay
        }
    }
}

extern "C" void kernel_launch(void* const* d_in, const int* in_sizes, int n_in,
                              void* d_out, int out_size) {
    (void)in_sizes; (void)n_in; (void)out_size;
    const float* emb = (const float*)d_in[0];
    float* out = (float*)d_out;
    cudaFuncSetAttribute(tile_kernel, cudaFuncAttributeMaxDynamicSharedMemorySize, SMEM_BYTES);
    split_kernel<<<BATCH * NPTS * DIM / (256 * 4), 256>>>(emb);
    tile_kernel<<<GRID, TPB, SMEM_BYTES>>>(out);
}

// round 16
// speedup vs baseline: 1.1804x; 1.1804x over previous
#include <cuda_runtime.h>
#include <cuda_fp16.h>
#include <math.h>
#include <stdint.h>

#define BATCH 8
#define NPTS  4096
#define DIM   64
#define NT    32                       // 128-row strips per batch
#define NTRI  (NT * (NT + 1) / 2)      // 528 tiles per batch (row-major upper tri)
#define SLOTS 37                       // chunks (CTAs) per batch
#define GRID  (BATCH * SLOTS)          // 296
#define TPB   256

// smem strip: 128 rows x 144 B stride -> conflict-free ldmatrix/STS
#define SROWB   144
#define STRIPB  (128 * SROWB)          // 18432 B
// layout: A0, A1, B0, B1, B2
#define SMEM_BYTES (5 * STRIPB)        // 92160 -> 2 CTAs/SM

// Single array scaled by sqrt(0.5*log2(e)): (s*a)·(s*b) = 0.5*log2(e)*a·b
__device__ __align__(16) __half g_s[BATCH * NPTS * DIM];
__device__ double g_partials[GRID];
__device__ unsigned g_cnt = 0;

__device__ __forceinline__ uint32_t smem_u32(const void* p) {
    uint32_t a;
    asm("{ .reg .u64 t; cvta.to.shared.u64 t, %1; cvt.u32.u64 %0, t; }" : "=r"(a) : "l"(p));
    return a;
}
template <int IMM>
__device__ __forceinline__ void ldsm4i(uint32_t* r, uint32_t addr) {
    asm volatile("ldmatrix.sync.aligned.m8n8.x4.shared.b16 {%0,%1,%2,%3}, [%4+%5];"
                 : "=r"(r[0]), "=r"(r[1]), "=r"(r[2]), "=r"(r[3])
                 : "r"(addr), "n"(IMM));
}
// NON-volatile MMA: ordering pinned by register dependencies only.
__device__ __forceinline__ void mma_acc(float* d, const uint32_t* a, const uint32_t* b) {
    asm("mma.sync.aligned.m16n8k16.row.col.f32.f16.f16.f32 "
        "{%0,%1,%2,%3}, {%4,%5,%6,%7}, {%8,%9}, {%0,%1,%2,%3};"
        : "+f"(d[0]), "+f"(d[1]), "+f"(d[2]), "+f"(d[3])
        : "r"(a[0]), "r"(a[1]), "r"(a[2]), "r"(a[3]), "r"(b[0]), "r"(b[1]));
}
// first-kstep variant: C = 0 -> writes acc fresh, no zeroing MOVs needed.
__device__ __forceinline__ void mma_zro(float* d, const uint32_t* a, const uint32_t* b) {
    asm("mma.sync.aligned.m16n8k16.row.col.f32.f16.f16.f32 "
        "{%0,%1,%2,%3}, {%4,%5,%6,%7}, {%8,%9}, {%10,%10,%10,%10};"
        : "=f"(d[0]), "=f"(d[1]), "=f"(d[2]), "=f"(d[3])
        : "r"(a[0]), "r"(a[1]), "r"(a[2]), "r"(a[3]), "r"(b[0]), "r"(b[1]), "f"(0.0f));
}
template <int DI, int SI>
__device__ __forceinline__ void cp16i(uint32_t dst, const __half* src) {
    asm volatile("cp.async.ca.shared.global [%0+%2], [%1+%3], 16;"
                 :: "r"(dst), "l"(src), "n"(DI), "n"(SI));
}
__device__ __forceinline__ float ex2f(float x) {
    float e;
    asm("ex2.approx.f32 %0, %1;" : "=f"(e) : "f"(x));
    return e;
}

// ---------------- 1) convert f32 -> fp16 scaled by sqrt(0.5*log2e) ----------------
__global__ __launch_bounds__(256) void split_kernel(const float* __restrict__ emb) {
    const float SQC = 0.84932180612318867f;  // sqrt(0.5*log2(e))
    int i = (blockIdx.x * 256 + threadIdx.x) * 4;
    float4 v = *(const float4*)(emb + i);
    float x[4] = {v.x, v.y, v.z, v.w};
    __half s[4];
    #pragma unroll
    for (int j = 0; j < 4; ++j) s[j] = __float2half(x[j] * SQC);
    *(uint2*)&g_s[i] = *(uint2*)s;
}

// ---------------- 2) persistent HMMA tile kernel (fused finalize) ----------------
// One 128-row strip load (4 cp16/thread), swizzle-free padded rows.
__device__ __forceinline__ void load_strip(uint32_t dst, const __half* src) {
    cp16i<0 * SROWB, 0 * DIM * 2>(dst, src);
    cp16i<32 * SROWB, 32 * DIM * 2>(dst, src);
    cp16i<64 * SROWB, 64 * DIM * 2>(dst, src);
    cp16i<96 * SROWB, 96 * DIM * 2>(dst, src);
}

// One tile's compute, k-steps rotated to start at R (R in {0,2}).
// First k-step uses mma_zro and interleaves the PREVIOUS tile's ex2 epilogue
// chunk-by-chunk ahead of the acc overwrite (MUFU fills the HMMA/ldsm shadow).
template <int R>
__device__ __forceinline__ void do_tile(
    float acc[4][4][4], float& facc, float pw,
    uint32_t aA0, uint32_t aA1, uint32_t aA2, uint32_t aA3,
    uint32_t aB0, uint32_t aB1)
{
    constexpr int K0 = (R & 3) * 32;
    constexpr int K1 = ((R + 1) & 3) * 32;
    constexpr int K2 = ((R + 2) & 3) * 32;
    constexpr int K3 = ((R + 3) & 3) * 32;

    float s0 = 0.f, s1 = 0.f, s2 = 0.f, s3 = 0.f;
    {
        uint32_t A[4][4], B[2][4];
        ldsm4i<K0>(A[0], aA0); ldsm4i<K0>(A[1], aA1);
        ldsm4i<K0>(A[2], aA2); ldsm4i<K0>(A[3], aA3);
        ldsm4i<K0>(B[0], aB0); ldsm4i<K0>(B[1], aB1);
        #pragma unroll
        for (int ma = 0; ma < 4; ++ma) {
            #pragma unroll
            for (int nb = 0; nb < 4; ++nb) {
                s0 += ex2f(acc[ma][nb][0]);
                s1 += ex2f(acc[ma][nb][1]);
                s2 += ex2f(acc[ma][nb][2]);
                s3 += ex2f(acc[ma][nb][3]);
            }
            #pragma unroll
            for (int nb = 0; nb < 4; ++nb)
                mma_zro(acc[ma][nb], A[ma], &B[nb >> 1][(nb & 1) * 2]);
        }
    }
    facc += pw * ((s0 + s1) + (s2 + s3));  // pw=0 on first iteration

    #define KSTEP_T(KO)                                                           \
    {                                                                             \
        uint32_t A[4][4], B[2][4];                                                \
        ldsm4i<KO>(A[0], aA0); ldsm4i<KO>(A[1], aA1);                             \
        ldsm4i<KO>(A[2], aA2); ldsm4i<KO>(A[3], aA3);                             \
        ldsm4i<KO>(B[0], aB0); ldsm4i<KO>(B[1], aB1);                             \
        _Pragma("unroll")                                                         \
        for (int ma = 0; ma < 4; ++ma)                                            \
            _Pragma("unroll")                                                     \
            for (int nb = 0; nb < 4; ++nb)                                        \
                mma_acc(acc[ma][nb], A[ma], &B[nb >> 1][(nb & 1) * 2]);           \
    }
    KSTEP_T(K1)
    KSTEP_T(K2)
    KSTEP_T(K3)
    #undef KSTEP_T
}

__global__ __launch_bounds__(TPB, 2) void tile_kernel(float* __restrict__ out) {
    extern __shared__ __align__(128) char smem[];
    __shared__ double redbuf[8];
    __shared__ int is_last_s;
    const uint32_t sbase = smem_u32(smem);
    const int tid = threadIdx.x;
    const int wid = tid >> 5;
    const int lid = tid & 31;
    const int wm = wid & 1;            // 2 warps along M (64 rows each)
    const int wn = wid >> 1;           // 4 warps along N (32 cols each)
    const bool hi = (wid >= 4);        // phase stagger: hi warps start at kstep 2

    const int bb   = blockIdx.x & 7;   // fixed batch per CTA
    const int slot = blockIdx.x >> 3;  // 0..36
    const __half* gS = g_s + (size_t)bb * NPTS * DIM;

    const int srcoff = (tid >> 3) * DIM + (tid & 7) * 8;                 // elements
    const uint32_t dsto = (uint32_t)((tid >> 3) * SROWB + (tid & 7) * 16);

    uint32_t offA[4];
    {
        int row = ((lid >> 3) & 1) * 8 + (lid & 7);
        int kc  = (lid >> 4) * 16;     // bytes
        #pragma unroll
        for (int ma = 0; ma < 4; ++ma)
            offA[ma] = (uint32_t)((wm * 64 + ma * 16 + row) * SROWB + kc);
    }
    uint32_t offB[2];
    {
        int row = (lid >> 4) * 8 + (lid & 7);
        int kc  = ((lid >> 3) & 1) * 16;
        #pragma unroll
        for (int np = 0; np < 2; ++np)
            offB[np] = (uint32_t)((wn * 32 + np * 16 + row) * SROWB + kc);
    }

    float facc = 0.0f;                 // running per-thread sum (all positive)
    float pw   = 0.0f;                 // weight of pending (previous) tile; 0 = none
    float acc[4][4][4];
    #pragma unroll
    for (int i = 0; i < 4; ++i)
        #pragma unroll
        for (int j = 0; j < 4; ++j)
            #pragma unroll
            for (int e = 0; e < 4; ++e) acc[i][j][e] = 0.0f;

    // Contiguous chunk [lo, hi_) of the row-major tri list: tiles (tn, tm>=tn).
    const int lo  = (NTRI * slot) / SLOTS;
    const int hi_ = (NTRI * (slot + 1)) / SLOTS;
    int tn = 0, rem = lo;
    while (rem >= NT - tn) { rem -= (NT - tn); ++tn; }
    int tm = tn + rem;

    int acur = 0;                      // current A slot (0/1)
    int bmod = lo % 3;                 // B slot rotation (uniform, advances every tile)

    // Prologue: A strip always; B strip unless the first tile is diagonal.
    load_strip(sbase + dsto, gS + tn * (128 * DIM) + srcoff);
    if (tm != tn)
        load_strip(sbase + (2 + bmod) * STRIPB + dsto, gS + tm * (128 * DIM) + srcoff);
    asm volatile("cp.async.commit_group;" ::: "memory");

    for (int j = lo; j < hi_; ++j) {
        const bool diag = (tm == tn);
        int ntn = tn, ntm = tm + 1;
        bool cross = (ntm == NT);
        if (cross) { ntn = tn + 1; ntm = ntn; }
        const int nbmod = (bmod == 2) ? 0 : bmod + 1;
        if (j + 1 < hi_) {
            if (cross)   // next tile is the diagonal of strip ntn: A load only
                load_strip(sbase + (acur ^ 1) * STRIPB + dsto,
                           gS + ntn * (128 * DIM) + srcoff);
            else
                load_strip(sbase + (2 + nbmod) * STRIPB + dsto,
                           gS + ntm * (128 * DIM) + srcoff);
            asm volatile("cp.async.commit_group;" ::: "memory");
            asm volatile("cp.async.wait_group 1;" ::: "memory");
        } else {
            asm volatile("cp.async.wait_group 0;" ::: "memory");
        }
        __syncthreads();               // single barrier: data ready; WAR distances >= 2

        const uint32_t Ab = sbase + acur * STRIPB;
        const uint32_t Bb = diag ? Ab : (sbase + (2 + bmod) * STRIPB);
        const uint32_t aA0 = Ab + offA[0], aA1 = Ab + offA[1];
        const uint32_t aA2 = Ab + offA[2], aA3 = Ab + offA[3];
        const uint32_t aB0 = Bb + offB[0], aB1 = Bb + offB[1];

        if (hi)
            do_tile<2>(acc, facc, pw, aA0, aA1, aA2, aA3, aB0, aB1);
        else
            do_tile<0>(acc, facc, pw, aA0, aA1, aA2, aA3, aB0, aB1);

        pw = diag ? 1.0f : 2.0f;
        if (cross) acur ^= 1;
        tn = ntn; tm = ntm; bmod = nbmod;
    }

    // Final pending epilogue.
    {
        float s0 = 0.f, s1 = 0.f, s2 = 0.f, s3 = 0.f;
        #pragma unroll
        for (int ma = 0; ma < 4; ++ma)
            #pragma unroll
            for (int nb = 0; nb < 4; ++nb) {
                s0 += ex2f(acc[ma][nb][0]);
                s1 += ex2f(acc[ma][nb][1]);
                s2 += ex2f(acc[ma][nb][2]);
                s3 += ex2f(acc[ma][nb][3]);
            }
        facc += pw * ((s0 + s1) + (s2 + s3));
    }

    // One block reduction in double at the very end.
    double acc_d = (double)facc;
    #pragma unroll
    for (int o = 16; o > 0; o >>= 1)
        acc_d += __shfl_down_sync(0xffffffffu, acc_d, o);
    if (lid == 0) redbuf[wid] = acc_d;
    __syncthreads();
    if (tid == 0) {
        double v = ((redbuf[0] + redbuf[1]) + (redbuf[2] + redbuf[3])) +
                   ((redbuf[4] + redbuf[5]) + (redbuf[6] + redbuf[7]));
        g_partials[blockIdx.x] = v;
    }

    // Fused finalize: last CTA reduces per-batch and writes the loss.
    __threadfence();
    if (tid == 0) {
        unsigned o = atomicAdd(&g_cnt, 1u);
        is_last_s = (o == GRID - 1) ? 1 : 0;
    }
    __syncthreads();
    if (is_last_s) {
        __threadfence();
        const int w = wid;             // warp w handles batch w
        double s = 0.0;
        for (int i = lid; i < SLOTS; i += 32)
            s += g_partials[(i << 3) + w];
        #pragma unroll
        for (int o = 16; o > 0; o >>= 1)
            s += __shfl_down_sync(0xffffffffu, s, o);
        if (lid == 0) redbuf[w] = log(s);
        __syncthreads();
        if (tid == 0) {
            double L = ((redbuf[0] + redbuf[1]) + (redbuf[2] + redbuf[3])) +
                       ((redbuf[4] + redbuf[5]) + (redbuf[6] + redbuf[7]));
            *out = (float)(L / 8.0);
            g_cnt = 0;                 // reset for next graph replay
        }
    }
}

extern "C" void kernel_launch(void* const* d_in, const int* in_sizes, int n_in,
                              void* d_out, int out_size) {
    (void)in_sizes; (void)n_in; (void)out_size;
    const float* emb = (const float*)d_in[0];
    float* out = (float*)d_out;
    cudaFuncSetAttribute(tile_kernel, cudaFuncAttributeMaxDynamicSharedMemorySize, SMEM_BYTES);
    split_kernel<<<BATCH * NPTS * DIM / (256 * 4), 256>>>(emb);
    tile_kernel<<<GRID, TPB, SMEM_BYTES>>>(out);
}